// round 16
// baseline (speedup 1.0000x reference)
#include <cuda_runtime.h>
#include <cuda_fp16.h>
#include <cstdint>

#define D_IN   1024
#define DMODEL 1024
#define BB     4
#define NN     2048
#define NH     16
#define HD     64
#define MTOT   (BB*NN)   // 8192

// Scratch (device globals; all fp16 pair-permuted layouts)
__device__ __half2 g_xh[(size_t)MTOT*512];        // X [row][512 pairs permuted]
__device__ __half2 g_wh[(size_t)4*DMODEL*512];    // W^T [n][512 pairs permuted]
__device__ __half2 g_qh[(size_t)BB*NH*NN*32];     // Q [bh][n][32 d-pairs permuted], scaled
__device__ __half2 g_kh[(size_t)BB*NH*NN*32];     // K [bh][n][32 d-pairs permuted]
__device__ __half2 g_vh[(size_t)BB*NH*HD*1024];   // V^T [bh][d][1024 tok-pairs permuted]
__device__ __half2 g_ch[(size_t)MTOT*512];        // ctx [row][512 pairs permuted]

// pair-permutation within a 16-pair (32-half) chunk:
// original pair (blk = jl>>3, j = jl&7) -> pos = (j&3)*4 + 2*blk + (j>>2)
__device__ __forceinline__ int pair_pos(int jl) {
    const int blk = jl >> 3, j = jl & 7;
    return (j & 3) * 4 + 2 * blk + (j >> 2);
}

__device__ __forceinline__ void mma_f16(float c[4], uint32_t a0, uint32_t a1,
                                        uint32_t a2, uint32_t a3,
                                        uint32_t b0, uint32_t b1) {
    asm("mma.sync.aligned.m16n8k16.row.col.f32.f16.f16.f32 "
        "{%0,%1,%2,%3},{%4,%5,%6,%7},{%8,%9},{%0,%1,%2,%3};"
        : "+f"(c[0]), "+f"(c[1]), "+f"(c[2]), "+f"(c[3])
        : "r"(a0), "r"(a1), "r"(a2), "r"(a3), "r"(b0), "r"(b1));
}

__device__ __forceinline__ void cp16(uint32_t s, const void* g) {
    asm volatile("cp.async.cg.shared.global [%0], [%1], 16;" :: "r"(s), "l"(g) : "memory");
}
#define CP_COMMIT() asm volatile("cp.async.commit_group;" ::: "memory")

__device__ __forceinline__ uint32_t h2bits(__half2 h) {
    return *reinterpret_cast<uint32_t*>(&h);
}

// ---------------------------------------------------------------------------
// Prep: fp16 conversion + pair permutation. X direct; W transposed to [n][k].
// ---------------------------------------------------------------------------
__global__ __launch_bounds__(256)
void prep_x(const float* __restrict__ x)
{
    const int idx = blockIdx.x * 256 + threadIdx.x;     // global pair index
    const int r = idx >> 9, p = idx & 511;
    const float2 v = *(const float2*)(x + (size_t)r * 1024 + p * 2);
    g_xh[(size_t)r * 512 + (p >> 4) * 16 + pair_pos(p & 15)] = __floats2half2_rn(v.x, v.y);
}

__global__ __launch_bounds__(256)
void prep_wt(const float* __restrict__ Wq, const float* __restrict__ Wk,
             const float* __restrict__ Wv, const float* __restrict__ Wo)
{
    __shared__ float t[32][33];
    const int slot = blockIdx.z;
    const float* w = (slot == 0) ? Wq : (slot == 1) ? Wk : (slot == 2) ? Wv : Wo;
    const int tx = threadIdx.x & 31, ty = threadIdx.x >> 5;
    const int n0 = blockIdx.x * 32, k0 = blockIdx.y * 32;
#pragma unroll
    for (int i = 0; i < 4; i++)       // t[k_local][n_local]
        t[ty + 8 * i][tx] = w[(size_t)(k0 + ty + 8 * i) * DMODEL + n0 + tx];
    __syncthreads();
    const int nl = threadIdx.x >> 3;
    __half2* dst = g_wh + (size_t)slot * DMODEL * 512;
#pragma unroll
    for (int it = 0; it < 2; it++) {
        const int kp = (threadIdx.x & 7) + 8 * it;      // pair within chunk (0..15)
        dst[(size_t)(n0 + nl) * 512 + blockIdx.y * 16 + pair_pos(kp)] =
            __floats2half2_rn(t[2 * kp][nl], t[2 * kp + 1][nl]);
    }
}

// ---------------------------------------------------------------------------
// FP16 GEMM (m16n8k16) — unchanged from round 15.
// ---------------------------------------------------------------------------
#define GS 3
#define STAGE_BYTES 32768                 // A 16KB + B 16KB, each [2][128][64B]
#define GEMM_SMEM (GS*STAGE_BYTES)        // 98304

__global__ __launch_bounds__(256, 2)
void gemm_f16(const float* __restrict__ bias,
              float* __restrict__ outp,
              int mode)
{
    extern __shared__ char smg[];
    const uint32_t sbase = (uint32_t)__cvta_generic_to_shared(smg);

    const int tid  = threadIdx.x;
    const int lane = tid & 31;
    const int warp = tid >> 5;
    const int wm   = warp >> 2;
    const int wn   = warp & 3;
    const int qr   = lane >> 2;
    const int qi   = lane & 3;
    const int bx   = blockIdx.x;
    const int by   = blockIdx.y;
    const int z    = blockIdx.z;

    const __half* A  = (mode == 0) ? (const __half*)g_xh : (const __half*)g_ch;
    const __half* Bt = (const __half*)g_wh + (size_t)((mode == 0) ? z : 3) * DMODEL * 1024;
    const __half* Abase = A + (size_t)by * 128 * 1024;
    const __half* Bbase = Bt + (size_t)bx * 128 * 1024;

    auto issue = [&](int kt) {
        const uint32_t base = sbase + (kt % GS) * STAGE_BYTES;
#pragma unroll
        for (int l = 0; l < 4; l++) {
            const int idx = l * 256 + tid;
            const int r = idx >> 3, u = idx & 7;
            const int cs = u >> 2, cc = u & 3;
            cp16(base + cs * 8192 + r * 64 + cc * 16,
                 Abase + (size_t)r * 1024 + kt * 64 + u * 8);
            cp16(base + 16384 + cs * 8192 + r * 64 + cc * 16,
                 Bbase + (size_t)r * 1024 + kt * 64 + u * 8);
        }
    };

    float c[4][4][4];
#pragma unroll
    for (int mf = 0; mf < 4; mf++)
#pragma unroll
        for (int nf = 0; nf < 4; nf++)
#pragma unroll
            for (int k = 0; k < 4; k++) c[mf][nf][k] = 0.f;

    issue(0); CP_COMMIT();
    issue(1); CP_COMMIT();

    const int KT = 1024 / 64;   // 16
    for (int kt = 0; kt < KT; kt++) {
        asm volatile("cp.async.wait_group 1;" ::: "memory");
        __syncthreads();
        if (kt + 2 < KT) issue(kt + 2);
        CP_COMMIT();

        const char* stg = smg + (kt % GS) * STAGE_BYTES;

#pragma unroll
        for (int cs = 0; cs < 2; cs++) {
            const char* As = stg + cs * 8192;
            const char* Bs = stg + 16384 + cs * 8192;
            uint4 fa0[4], fa1[4], fb[4];
#pragma unroll
            for (int mf = 0; mf < 4; mf++) {
                const int rr = wm * 64 + mf * 16 + qr;
                fa0[mf] = *(const uint4*)(As + rr * 64 + qi * 16);
                fa1[mf] = *(const uint4*)(As + (rr + 8) * 64 + qi * 16);
            }
#pragma unroll
            for (int nf = 0; nf < 4; nf++) {
                const int n = wn * 32 + nf * 8 + qr;
                fb[nf] = *(const uint4*)(Bs + n * 64 + qi * 16);
            }
#pragma unroll
            for (int mf = 0; mf < 4; mf++)
#pragma unroll
                for (int nf = 0; nf < 4; nf++) {
                    mma_f16(c[mf][nf], fa0[mf].x, fa1[mf].x, fa0[mf].y, fa1[mf].y,
                            fb[nf].x, fb[nf].y);
                    mma_f16(c[mf][nf], fa0[mf].z, fa1[mf].z, fa0[mf].w, fa1[mf].w,
                            fb[nf].z, fb[nf].w);
                }
        }
    }

    // ---- epilogue ----
    if (mode == 0) {
        const float mult = (z == 0) ? (0.125f * 1.44269504088896f) : 1.f;
#pragma unroll
        for (int mf = 0; mf < 4; mf++)
#pragma unroll
            for (int nf = 0; nf < 4; nf++) {
                const int mlo = by * 128 + wm * 64 + mf * 16 + qr;
                const int col = bx * 128 + wn * 32 + nf * 8 + 2 * qi;   // even
                const int h_ = col >> 6, d = col & 63;
                if (z == 2) {
                    __half* vb = (__half*)g_vh;
#pragma unroll
                    for (int rs = 0; rs < 2; rs++) {
                        const int m = mlo + 8 * rs;
                        const int b_ = m >> 11, n_ = m & (NN - 1);
                        const int tp = n_ >> 1;
                        const int hidx = (tp >> 4) * 32 + pair_pos(tp & 15) * 2 + (n_ & 1);
                        const size_t rowb = ((size_t)(b_ * NH + h_) * HD);
                        vb[(rowb + d) * 2048 + hidx]     = __float2half_rn(c[mf][nf][2 * rs + 0]);
                        vb[(rowb + d + 1) * 2048 + hidx] = __float2half_rn(c[mf][nf][2 * rs + 1]);
                    }
                } else {
                    __half2* O = (z == 0) ? g_qh : g_kh;
                    const int dp = d >> 1;
                    const int offs = (dp >> 4) * 16 + pair_pos(dp & 15);
#pragma unroll
                    for (int rs = 0; rs < 2; rs++) {
                        const int m = mlo + 8 * rs;
                        const int b_ = m >> 11, n_ = m & (NN - 1);
                        O[(((size_t)(b_ * NH + h_)) * NN + n_) * 32 + offs] =
                            __floats2half2_rn(c[mf][nf][2 * rs] * mult,
                                              c[mf][nf][2 * rs + 1] * mult);
                    }
                }
            }
    } else {
#pragma unroll
        for (int mf = 0; mf < 4; mf++)
#pragma unroll
            for (int nf = 0; nf < 4; nf++) {
                const int mlo = by * 128 + wm * 64 + mf * 16 + qr;
                const int col = bx * 128 + wn * 32 + nf * 8 + 2 * qi;
                const float2 bv = *(const float2*)(bias + col);
#pragma unroll
                for (int rs = 0; rs < 2; rs++) {
                    const int m = mlo + 8 * rs;
                    float2 ov;
                    ov.x = c[mf][nf][2 * rs] + bv.x;
                    ov.y = c[mf][nf][2 * rs + 1] + bv.y;
                    *(float2*)(outp + (size_t)m * DMODEL + col) = ov;
                }
            }
    }
}

// ---------------------------------------------------------------------------
// Flash attention (causal), fp16 m16n8k16. BR=64: 128 thr = 4 warps x 16 rows.
// TWO kt-tiles per barrier, 4-buffer ring (64KB smem): S(t0) and S(t1) are
// computed back-to-back so the independent S(t1) MMA block fills the
// softmax(t0) latency hole; barriers per tile are halved. Loads for the next
// pair are issued right after the barrier and overlap the full pair-compute.
// Math order per tile identical to r15 -> bit-identical results.
// ---------------------------------------------------------------------------
__global__ __launch_bounds__(128, 3)
void attn_f16()
{
    __shared__ char sm[65536];   // K: [4 buf][2 cs][64 tok][64B]; V at +32768

    const int tid  = threadIdx.x;
    const int lane = tid & 31;
    const int w    = tid >> 5;
    const int qr   = lane >> 2;
    const int qi   = lane & 3;
    const int qt   = 31 - blockIdx.x;      // longest CTAs first
    const int bh   = blockIdx.y;

    const __half* Qg = (const __half*)g_qh + ((size_t)bh * NN + qt * 64) * 64;
    const __half* Kg = (const __half*)g_kh + (size_t)bh * NN * 64;
    const __half* Vg = (const __half*)g_vh + (size_t)bh * HD * 2048;

    const uint32_t sK = (uint32_t)__cvta_generic_to_shared(sm);

    auto issueKV = [&](int kt) {
        const int buf = kt & 3;
#pragma unroll
        for (int l = 0; l < 4; l++) {
            const int idx = l * 128 + tid;
            const int r = idx >> 3, u = idx & 7;         // r: token (K) or d (V)
            const int cs = u >> 2, cc = u & 3;
            cp16(sK + buf * 8192 + cs * 4096 + r * 64 + cc * 16,
                 Kg + (size_t)(kt * 64 + r) * 64 + u * 8);
            cp16(sK + 32768 + buf * 8192 + cs * 4096 + r * 64 + cc * 16,
                 Vg + (size_t)r * 2048 + (kt * 2 + cs) * 32 + cc * 8);
        }
    };

    const int ar = w * 16 + qr;

    // Q fragments for the whole loop: 4 LDG.128
    uint4 ql[2], qh_[2];
#pragma unroll
    for (int cs = 0; cs < 2; cs++) {
        ql[cs]  = *(const uint4*)(Qg + ar * 64 + cs * 32 + qi * 8);
        qh_[cs] = *(const uint4*)(Qg + (ar + 8) * 64 + cs * 32 + qi * 8);
    }

    float m0 = -1e30f, m1 = -1e30f, l0 = 0.f, l1 = 0.f;
    float o[8][4];
#pragma unroll
    for (int nf = 0; nf < 8; nf++)
#pragma unroll
        for (int ci = 0; ci < 4; ci++) o[nf][ci] = 0.f;

    // S = Q K^T for one tile
    auto computeS = [&](float (&s)[8][4], const char* Kb) {
#pragma unroll
        for (int nf = 0; nf < 8; nf++)
#pragma unroll
            for (int ci = 0; ci < 4; ci++) s[nf][ci] = 0.f;
#pragma unroll
        for (int cs = 0; cs < 2; cs++) {
#pragma unroll
            for (int nf = 0; nf < 8; nf++) {
                const int kr = nf * 8 + qr;
                const uint4 kb = *(const uint4*)(Kb + cs * 4096 + kr * 64 + qi * 16);
                mma_f16(s[nf], ql[cs].x, qh_[cs].x, ql[cs].y, qh_[cs].y, kb.x, kb.y);
                mma_f16(s[nf], ql[cs].z, qh_[cs].z, ql[cs].w, qh_[cs].w, kb.z, kb.w);
            }
        }
    };

    // mask (if diagonal) + online softmax + P pack + PV accumulate
    auto softmaxPV = [&](float (&s)[8][4], const char* Vb, int t) {
        if (t == qt) {
            const int rr0 = ar, rr1 = ar + 8;
#pragma unroll
            for (int nf = 0; nf < 8; nf++) {
                const int cb = nf * 8 + 2 * qi;
                if (cb     > rr0) s[nf][0] = -1e30f;
                if (cb + 1 > rr0) s[nf][1] = -1e30f;
                if (cb     > rr1) s[nf][2] = -1e30f;
                if (cb + 1 > rr1) s[nf][3] = -1e30f;
            }
        }

        float mx0 = -1e30f, mx1 = -1e30f;
#pragma unroll
        for (int nf = 0; nf < 8; nf++) {
            mx0 = fmaxf(mx0, fmaxf(s[nf][0], s[nf][1]));
            mx1 = fmaxf(mx1, fmaxf(s[nf][2], s[nf][3]));
        }
        mx0 = fmaxf(mx0, __shfl_xor_sync(0xffffffffu, mx0, 1));
        mx0 = fmaxf(mx0, __shfl_xor_sync(0xffffffffu, mx0, 2));
        mx1 = fmaxf(mx1, __shfl_xor_sync(0xffffffffu, mx1, 1));
        mx1 = fmaxf(mx1, __shfl_xor_sync(0xffffffffu, mx1, 2));

        const float mn0 = fmaxf(m0, mx0), mn1 = fmaxf(m1, mx1);
        const float cf0 = exp2f(m0 - mn0), cf1 = exp2f(m1 - mn1);
        m0 = mn0; m1 = mn1;

        uint32_t plo[8], phi[8];
        float rs0 = 0.f, rs1 = 0.f;
#pragma unroll
        for (int nf = 0; nf < 8; nf++) {
            const __half2 h0 = __floats2half2_rn(exp2f(s[nf][0] - mn0),
                                                 exp2f(s[nf][1] - mn0));
            const __half2 h1 = __floats2half2_rn(exp2f(s[nf][2] - mn1),
                                                 exp2f(s[nf][3] - mn1));
            const float2 f0 = __half22float2(h0), f1 = __half22float2(h1);
            rs0 += f0.x + f0.y;
            rs1 += f1.x + f1.y;
            plo[nf] = h2bits(h0);
            phi[nf] = h2bits(h1);
        }
        rs0 += __shfl_xor_sync(0xffffffffu, rs0, 1);
        rs0 += __shfl_xor_sync(0xffffffffu, rs0, 2);
        rs1 += __shfl_xor_sync(0xffffffffu, rs1, 1);
        rs1 += __shfl_xor_sync(0xffffffffu, rs1, 2);
        l0 = l0 * cf0 + rs0;
        l1 = l1 * cf1 + rs1;
#pragma unroll
        for (int nf = 0; nf < 8; nf++) {
            o[nf][0] *= cf0; o[nf][1] *= cf0;
            o[nf][2] *= cf1; o[nf][3] *= cf1;
        }

#pragma unroll
        for (int cs = 0; cs < 2; cs++) {
            const int t0 = 2 * cs, t1 = 2 * cs + 1;
#pragma unroll
            for (int nf = 0; nf < 8; nf++) {
                const int dr = nf * 8 + qr;
                const uint4 vb = *(const uint4*)(Vb + cs * 4096 + dr * 64 + qi * 16);
                mma_f16(o[nf], plo[2 * t0], phi[2 * t0], plo[2 * t0 + 1], phi[2 * t0 + 1],
                        vb.x, vb.y);
                mma_f16(o[nf], plo[2 * t1], phi[2 * t1], plo[2 * t1 + 1], phi[2 * t1 + 1],
                        vb.z, vb.w);
            }
        }
    };

    const int nkt = qt + 1;

    issueKV(0);
    if (nkt > 1) issueKV(1);
    CP_COMMIT();

    int kt = 0;
    const int npairs = nkt >> 1;
    for (int i = 0; i < npairs; i++, kt += 2) {
        asm volatile("cp.async.wait_group 0;" ::: "memory");
        __syncthreads();
        if (kt + 2 < nkt) issueKV(kt + 2);
        if (kt + 3 < nkt) issueKV(kt + 3);
        CP_COMMIT();

        const char* Kb0 = sm + ((kt    ) & 3) * 8192;
        const char* Kb1 = sm + ((kt + 1) & 3) * 8192;
        const char* Vb0 = sm + 32768 + ((kt    ) & 3) * 8192;
        const char* Vb1 = sm + 32768 + ((kt + 1) & 3) * 8192;

        float s0[8][4], s1[8][4];
        computeS(s0, Kb0);
        computeS(s1, Kb1);      // independent MMA block: fills softmax(t0) hole
        softmaxPV(s0, Vb0, kt);
        softmaxPV(s1, Vb1, kt + 1);
    }
    if (nkt & 1) {              // tail: the diagonal tile
        asm volatile("cp.async.wait_group 0;" ::: "memory");
        __syncthreads();
        const char* Kb = sm + ((nkt - 1) & 3) * 8192;
        const char* Vb = sm + 32768 + ((nkt - 1) & 3) * 8192;
        float s0[8][4];
        computeS(s0, Kb);
        softmaxPV(s0, Vb, nkt - 1);
    }

    // ---- normalize + write ctx (fp16 pair-permuted for out-proj) ----
    const int b_ = bh >> 4, h_ = bh & 15;
    const float inv0 = 1.f / l0, inv1 = 1.f / l1;
#pragma unroll
    for (int nf = 0; nf < 8; nf++) {
        const int n0 = qt * 64 + ar;
        const int cb = h_ * 64 + nf * 8 + 2 * qi;   // even
        const int p  = cb >> 1;
        const int offs = (p >> 4) * 16 + pair_pos(p & 15);
        g_ch[(size_t)(b_ * NN + n0) * 512 + offs] =
            __floats2half2_rn(o[nf][0] * inv0, o[nf][1] * inv0);
        g_ch[(size_t)(b_ * NN + n0 + 8) * 512 + offs] =
            __floats2half2_rn(o[nf][2] * inv1, o[nf][3] * inv1);
    }
}

// ---------------------------------------------------------------------------
extern "C" void kernel_launch(void* const* d_in, const int* in_sizes, int n_in,
                              void* d_out, int out_size)
{
    const float* x  = (const float*)d_in[0];
    const float* Wq = (const float*)d_in[1];
    const float* Wk = (const float*)d_in[2];
    const float* Wv = (const float*)d_in[3];
    const float* Wo = (const float*)d_in[4];
    const float* bo = (const float*)d_in[5];
    float* out = (float*)d_out;

    cudaFuncSetAttribute(gemm_f16, cudaFuncAttributeMaxDynamicSharedMemorySize, GEMM_SMEM);

    // one-time fp16 conversion + layout transforms
    prep_x<<<(MTOT * 512) / 256, 256>>>(x);
    prep_wt<<<dim3(DMODEL / 32, D_IN / 32, 4), 256>>>(Wq, Wk, Wv, Wo);

    // QKV projections -> g_qh/g_kh (frag layout), g_vh (transposed)
    gemm_f16<<<dim3(8, 64, 3), 256, GEMM_SMEM>>>(nullptr, nullptr, 0);
    // causal flash attention (2 tiles per barrier, 4-buffer ring)
    attn_f16<<<dim3(32, 64), 128>>>();
    // output projection + bias
    gemm_f16<<<dim3(8, 64, 1), 256, GEMM_SMEM>>>(bo, out, 1);
}